// round 16
// baseline (speedup 1.0000x reference)
#include <cuda_runtime.h>
#include <cuda_fp16.h>
#include <math.h>
#include <stdint.h>

#define BB    2
#define SS    2048
#define DD    512
#define HH    8
#define DHH   64
#define INNER 512
#define MTOT  (BB*SS)      // 4096
#define NQKV  (3*INNER)    // 1536

// ---------------- scratch ----------------
__device__ float g_scale[2];
__device__ float g_t[2048];
__device__ float g_p2[16];
__device__ int   g_cnt;
__device__ __half g_Q[BB*HH*SS*DHH];        // [bh][row][dim] fp16, pre-scaled
__device__ __half g_K[BB*HH*SS*DHH];        // [bh][key][dim] fp16
__device__ __half g_V[BB*HH*SS*DHH];        // [bh][dim][key] fp16 (TRANSPOSED)
__device__ __half g_O[(size_t)MTOT*INNER];  // fp16
__device__ __half g_xT[(size_t)MTOT*DD];    // fp16 of x
__device__ __half g_WqT[(size_t)NQKV*DD];   // fp16 of W_qkv
__device__ __half g_WoT[(size_t)DD*INNER];  // fp16 of W_out

// ---------------- helpers ----------------
__device__ __forceinline__ uint32_t smem_u32(const void* p) {
    uint32_t a;
    asm("{ .reg .u64 t; cvta.to.shared.u64 t, %1; cvt.u32.u64 %0, t; }" : "=r"(a) : "l"(p));
    return a;
}
__device__ __forceinline__ uint32_t h2pack(float a, float b) {
    __half2 h = __floats2half2_rn(a, b);
    return *(uint32_t*)&h;
}
__device__ __forceinline__ uint32_t ex2h2(uint32_t x) {
    uint32_t y;
    asm("ex2.approx.f16x2 %0, %1;" : "=r"(y) : "r"(x));
    return y;
}
__device__ __forceinline__ void mma_f16(float* d, const uint32_t* a, const uint32_t* b) {
    asm volatile("mma.sync.aligned.m16n8k16.row.col.f32.f16.f16.f32 "
                 "{%0,%1,%2,%3}, {%4,%5,%6,%7}, {%8,%9}, {%0,%1,%2,%3};"
                 : "+f"(d[0]), "+f"(d[1]), "+f"(d[2]), "+f"(d[3])
                 : "r"(a[0]), "r"(a[1]), "r"(a[2]), "r"(a[3]), "r"(b[0]), "r"(b[1]));
}
__device__ __forceinline__ void ldsm4(uint32_t& r0, uint32_t& r1, uint32_t& r2, uint32_t& r3,
                                      uint32_t addr) {
    asm volatile("ldmatrix.sync.aligned.m8n8.x4.shared.b16 {%0,%1,%2,%3}, [%4];"
                 : "=r"(r0), "=r"(r1), "=r"(r2), "=r"(r3) : "r"(addr));
}
__device__ __forceinline__ void cp16(uint32_t dst, const void* src) {
    asm volatile("cp.async.cg.shared.global [%0], [%1], 16;" :: "r"(dst), "l"(src));
}
#define CP_COMMIT() asm volatile("cp.async.commit_group;" ::: "memory")
#define CP_WAIT(N)  asm volatile("cp.async.wait_group %0;" :: "n"(N) : "memory")

__device__ __forceinline__ __half2 u2h2(uint32_t u) { return *(__half2*)&u; }

// ---------------------------------------------------------------------------
// Fused kernel 1: fp32->fp16 conversion (blocks 0..1535) + sn1 (blocks 1536..1791)
// ---------------------------------------------------------------------------
#define M1 (MTOT*DD/8)
#define M2 (NQKV*DD/8)
#define M3 (DD*INNER/8)
#define CVT_BLOCKS ((M1 + M2 + M3) / 256)     // 1536

__global__ __launch_bounds__(256) void cvtsn1_kernel(const float4* __restrict__ x,
                                                     const float4* __restrict__ wq4,
                                                     const float4* __restrict__ wo4,
                                                     const float* __restrict__ Wq,
                                                     const float* __restrict__ Wo,
                                                     const float* __restrict__ uq,
                                                     const float* __restrict__ uo)
{
    if (blockIdx.x == 0 && threadIdx.x == 0) g_cnt = 0;

    if (blockIdx.x < CVT_BLOCKS) {
        const int i = blockIdx.x * 256 + threadIdx.x;
        const float4* src;
        uint4* dst;
        int j = i;
        if (j < M1)              { src = x;   dst = (uint4*)g_xT; }
        else if ((j -= M1) < M2) { src = wq4; dst = (uint4*)g_WqT; }
        else                     { j -= M2; src = wo4; dst = (uint4*)g_WoT; }
        float4 v0 = src[2 * j], v1 = src[2 * j + 1];
        uint4 o;
        o.x = h2pack(v0.x, v0.y);
        o.y = h2pack(v0.z, v0.w);
        o.z = h2pack(v1.x, v1.y);
        o.w = h2pack(v1.z, v1.w);
        dst[j] = o;
        return;
    }

    const int lb = blockIdx.x - CVT_BLOCKS;   // 0..255
    const int w = threadIdx.x >> 5, lane = threadIdx.x & 31;
    const bool isQ = lb < 192;
    const int rl = (isQ ? lb : lb - 192) * 8 + w;
    const float4* Wr = (const float4*)((isQ ? Wq : Wo) + (size_t)rl * DD);
    const float4* u4 = (const float4*)(isQ ? uq : uo);
    float acc = 0.f;
    for (int c = lane; c < DD / 4; c += 32) {
        float4 a = Wr[c], b = u4[c];
        acc += a.x * b.x + a.y * b.y + a.z * b.z + a.w * b.w;
    }
    #pragma unroll
    for (int s = 16; s > 0; s >>= 1) acc += __shfl_xor_sync(0xFFFFFFFF, acc, s);
    if (lane == 0) g_t[(isQ ? 0 : NQKV) + rl] = acc;
}

// ---------------------------------------------------------------------------
// Fused kernel 2: sn2 (16 blocks) + last-block finalize of both scales.
// ---------------------------------------------------------------------------
__global__ __launch_bounds__(256) void sn2fin_kernel(const float* __restrict__ Wq,
                                                     const float* __restrict__ Wo,
                                                     const float* __restrict__ s0,
                                                     const float* __restrict__ s1)
{
    __shared__ float red[256];
    __shared__ int isLast;
    const int t = threadIdx.x;
    const bool isQ = blockIdx.x < 8;
    const int cb = (isQ ? blockIdx.x : blockIdx.x - 8) * 64;
    const int R = isQ ? NQKV : INNER;
    const float* W = isQ ? Wq : Wo;
    const float* tv = g_t + (isQ ? 0 : NQKV);
    const int c = cb + (t & 63);
    const int seg = t >> 6;
    float acc = 0.f;
    for (int r = seg; r < R; r += 4) acc += W[(size_t)r * DD + c] * tv[r];
    red[t] = acc;
    __syncthreads();
    float s2 = 0.f;
    if (seg == 0) {
        float s = red[t] + red[t + 64] + red[t + 128] + red[t + 192];
        s2 = s * s;
    }
    red[t] = s2;
    __syncthreads();
    if (t < 32) red[t] += red[t + 32];
    __syncwarp();
    if (t < 32) {
        float v = red[t];
        #pragma unroll
        for (int s = 16; s > 0; s >>= 1) v += __shfl_xor_sync(0xFFFFFFFF, v, s);
        if (t == 0) g_p2[blockIdx.x] = v;
    }

    if (t == 0) {
        __threadfence();
        isLast = (atomicAdd(&g_cnt, 1) == 15);
    }
    __syncthreads();
    if (!isLast) return;

    float a0 = 0.f, a1 = 0.f;
    for (int r = t; r < NQKV; r += 256) { float v = g_t[r]; a0 += v * v; }
    for (int r = t; r < INNER; r += 256) { float v = g_t[NQKV + r]; a1 += v * v; }
    __syncthreads();
    red[t] = a0;
    __syncthreads();
    for (int s = 128; s > 0; s >>= 1) { if (t < s) red[t] += red[t + s]; __syncthreads(); }
    const float tt0 = red[0];
    __syncthreads();
    red[t] = a1;
    __syncthreads();
    for (int s = 128; s > 0; s >>= 1) { if (t < s) red[t] += red[t + s]; __syncthreads(); }
    const float tt1 = red[0];
    if (t == 0) {
        float ss0 = 0.f, ss1 = 0.f;
        #pragma unroll
        for (int i = 0; i < 8; ++i) { ss0 += g_p2[i]; ss1 += g_p2[8 + i]; }
        g_scale[0] = s0[0] * sqrtf(tt0 / ss0);
        g_scale[1] = s1[0] * sqrtf(tt1 / ss1);
    }
}

// ---------------------------------------------------------------------------
// fp16 mma GEMM (m16n8k16), 3-stage cp.async, K-chunk 32, ONE barrier/chunk.
// Templated on MTCNT: M-tile = MTCNT*32 (gemm0: 128x128, gemm1: 64x128 for
// 256-CTA grid balance). EPI=0: scatter Q/K/V(T). EPI=1: A=g_O, +bias fp32.
// ---------------------------------------------------------------------------
#define GST 40                                 // halves per row (80 B)
#define GEMM_SMEM0 (3 * (128 + 128) * GST * 2) // 61440 B
#define GEMM_SMEM1 (3 * (64 + 128) * GST * 2)  // 46080 B

template<int EPI, int MTCNT>
__global__ __launch_bounds__(256) void gemm_mma_kernel(const __half* __restrict__ Ain,
                                                       const __half* __restrict__ B,
                                                       const float* __restrict__ bias,
                                                       float* __restrict__ Cout,
                                                       int Ndim, int Kdim, int sidx,
                                                       const float* __restrict__ temp)
{
    constexpr int ATILE = MTCNT * 32;
    extern __shared__ __half dsmh[];
    __half* sA = dsmh;                         // [3][ATILE*GST]
    __half* sB = dsmh + 3 * ATILE * GST;       // [3][128*GST]

    const __half* A = (EPI == 1) ? (const __half*)g_O : Ain;
    const int tid = threadIdx.x;
    const int wid = tid >> 5, lane = tid & 31;
    const int g = lane >> 2, t = lane & 3;
    const int wm = (wid >> 2) * (MTCNT * 16);
    const int wn = (wid & 3) * 32;
    const int m0 = blockIdx.y * ATILE, n0 = blockIdx.x * 128;

    const uint32_t aBase = smem_u32(sA);
    const uint32_t bBase = smem_u32(sB);

    const int aRow = wm + (lane & 15);                 // + mt*16
    const int aColH = (lane >> 4) * 8;                 // + ks*16
    const int bRow = wn + (lane & 7);                  // + nt*8
    const int bColH = (lane >> 3) * 8;                 // covers k0..31

    auto prefetch = [&](int st, int k0) {
        #pragma unroll
        for (int p = 0; p < MTCNT / 2; ++p) {          // A: ATILE rows
            const int slot = tid + p * 256;
            const int row = slot >> 2, q = slot & 3;
            cp16(aBase + (uint32_t)(st * ATILE * GST + row * GST + q * 8) * 2,
                 A + (size_t)(m0 + row) * Kdim + k0 + q * 8);
        }
        #pragma unroll
        for (int p = 0; p < 2; ++p) {                  // B: 128 rows
            const int slot = tid + p * 256;
            const int row = slot >> 2, q = slot & 3;
            cp16(bBase + (uint32_t)(st * 128 * GST + row * GST + q * 8) * 2,
                 B + (size_t)(n0 + row) * Kdim + k0 + q * 8);
        }
        CP_COMMIT();
    };

    float acc[MTCNT][4][4];
    #pragma unroll
    for (int i = 0; i < MTCNT; ++i)
        #pragma unroll
        for (int j = 0; j < 4; ++j)
            #pragma unroll
            for (int r = 0; r < 4; ++r) acc[i][j][r] = 0.f;

    const int nk = Kdim / 32;
    prefetch(0, 0);
    prefetch(1, 32);

    for (int kc = 0; kc < nk; ++kc) {
        if (kc + 1 < nk) { CP_WAIT(1); } else { CP_WAIT(0); }
        __syncthreads();
        if (kc + 2 < nk) prefetch((kc + 2) % 3, (kc + 2) * 32);

        const int cur = kc % 3;
        const uint32_t aCur = aBase + (uint32_t)(cur * ATILE * GST) * 2;
        const uint32_t bCur = bBase + (uint32_t)(cur * 128 * GST) * 2;

        uint32_t bf[4][4];
        #pragma unroll
        for (int nt = 0; nt < 4; ++nt)
            ldsm4(bf[nt][0], bf[nt][1], bf[nt][2], bf[nt][3],
                  bCur + (uint32_t)((bRow + nt * 8) * GST + bColH) * 2);

        #pragma unroll
        for (int ks = 0; ks < 2; ++ks) {
            uint32_t af[MTCNT][4];
            #pragma unroll
            for (int mt = 0; mt < MTCNT; ++mt)
                ldsm4(af[mt][0], af[mt][1], af[mt][2], af[mt][3],
                      aCur + (uint32_t)((aRow + mt * 16) * GST + aColH + ks * 16) * 2);
            #pragma unroll
            for (int mt = 0; mt < MTCNT; ++mt)
                #pragma unroll
                for (int nt = 0; nt < 4; ++nt)
                    mma_f16(acc[mt][nt], af[mt], &bf[nt][ks * 2]);
        }
    }

    const float sc = g_scale[sidx];
    const float tsc = (EPI == 0) ? (expf(temp[0]) * 1.4426950408889634f) : 0.f;

    #pragma unroll
    for (int mt = 0; mt < MTCNT; ++mt) {
        #pragma unroll
        for (int half = 0; half < 2; ++half) {
            const int m = m0 + wm + mt * 16 + g + half * 8;
            #pragma unroll
            for (int nt = 0; nt < 4; ++nt) {
                const int n = n0 + wn + nt * 8 + 2 * t;
                float v0 = acc[mt][nt][half * 2 + 0] * sc;
                float v1 = acc[mt][nt][half * 2 + 1] * sc;
                if (EPI == 0) {
                    const int seg = n >> 9, nn = n & 511;
                    const int head = nn >> 6, d = nn & 63;
                    const int b = m >> 11, s = m & 2047;
                    if (seg == 0) { v0 *= tsc; v1 *= tsc; }
                    if (seg == 2) {   // V transposed: [bh][dim][key]
                        __half* dst = g_V + (((size_t)(b * HH + head) * DHH + d) * SS + s);
                        dst[0]  = __float2half_rn(v0);
                        dst[SS] = __float2half_rn(v1);
                    } else {
                        __half* dst = (seg == 0) ? g_Q : g_K;
                        uint32_t pk = h2pack(v0, v1);
                        *(uint32_t*)(dst + (((size_t)(b * HH + head) * SS + s) * DHH + d)) = pk;
                    }
                } else {
                    float2 bb = *(const float2*)(bias + n);
                    float2 v = make_float2(v0 + bb.x, v1 + bb.y);
                    *(float2*)(Cout + (size_t)m * Ndim + n) = v;
                }
            }
        }
    }
}

// ---------------------------------------------------------------------------
// Flash attention, fp16 m16n8k16, register-resident P.
// This round: PV(h1) DEFERRED across the tile boundary (NSTG=4 keeps the old
// V buffer alive), so both ex2 pack phases are followed by independent tensor
// work. Order: [PV1(prev)] QK0 pack0 QK1 PV0 pack1. Tail PV1 peeled.
// ---------------------------------------------------------------------------
#define AST 72                     // halves per row (144 B)
#define NSTG 4
#define ATTN_SMEM (NSTG * 2 * 64 * AST * 2)   // 73728 B
#define NTILES 32

__global__ __launch_bounds__(256, 2) void attn_kernel()
{
    extern __shared__ __half dsmh[];

    const int bh  = blockIdx.x;
    const int row0 = blockIdx.y * 128;
    const int tid = threadIdx.x;
    const int wid = tid >> 5, lane = tid & 31;
    const int g = lane >> 2, t = lane & 3;
    const int wrow = row0 + wid * 16;

    const uint32_t* Qu = (const uint32_t*)(g_Q + (size_t)bh * SS * DHH);  // 32 words/row
    const __half* Kg = g_K + (size_t)bh * SS * DHH;
    const __half* Vg = g_V + (size_t)bh * SS * DHH;   // [dim][key]

    const uint32_t kBase = smem_u32(dsmh);
    const uint32_t vBase = smem_u32(dsmh + NSTG * 64 * AST);

    const int kbRow = (lane & 7);             // + nt*8 (key row)
    const int kbColH = (lane >> 3) * 8;       // + c*32 (dim col)
    const int vbRow = (lane & 7);             // + nt*8 (dim row)
    const int vbColH = (lane >> 3) * 8;       // + 0/32 (key col)

    auto prefetch = [&](int buf, int jt) {
        #pragma unroll
        for (int p = 0; p < 2; ++p) {          // K: 64 keys x 64 halves = 512 cp16
            const int s = tid + p * 256;
            const int row = s >> 3, q = s & 7;
            cp16(kBase + (uint32_t)(buf * 64 * AST + row * AST + q * 8) * 2,
                 Kg + (size_t)(jt + row) * DHH + q * 8);
        }
        #pragma unroll
        for (int p = 0; p < 2; ++p) {          // V: 64 dims x 64 keys
            const int s = tid + p * 256;
            const int row = s >> 3, q = s & 7;
            cp16(vBase + (uint32_t)(buf * 64 * AST + row * AST + q * 8) * 2,
                 Vg + (size_t)row * SS + jt + q * 8);
        }
        CP_COMMIT();
    };

    prefetch(0, 0);
    prefetch(1, 64);

    // Q a-frags (direct LDG; g_Q pre-scaled fp16): 4 ksteps of k16
    uint32_t qf[4][4];
    #pragma unroll
    for (int ks = 0; ks < 4; ++ks) {
        qf[ks][0] = Qu[(wrow + g    ) * 32 + ks * 8 + t    ];
        qf[ks][1] = Qu[(wrow + g + 8) * 32 + ks * 8 + t    ];
        qf[ks][2] = Qu[(wrow + g    ) * 32 + ks * 8 + t + 4];
        qf[ks][3] = Qu[(wrow + g + 8) * 32 + ks * 8 + t + 4];
    }

    float of[8][4];
    #pragma unroll
    for (int nt = 0; nt < 8; ++nt)
        #pragma unroll
        for (int r = 0; r < 4; ++r) of[nt][r] = 0.f;
    float l0 = 0.f, l1 = 0.f;
    uint32_t p1A[4], p1B[4];   // deferred PV(h1) operands (live across tiles)

    const int r0 = wrow + g, r1 = wrow + g + 8;

    for (int it = 0; it < NTILES; ++it) {
        if (it + 1 < NTILES) { CP_WAIT(1); } else { CP_WAIT(0); }
        __syncthreads();
        if (it + 2 < NTILES) prefetch((it + 2) & 3, (it + 2) * 64);

        const int cur = it & 3;
        const uint32_t kCur = kBase + (uint32_t)(cur * 64 * AST) * 2;
        const uint32_t vCur = vBase + (uint32_t)(cur * 64 * AST) * 2;
        const int jt = it * 64;
        const bool band = (jt < wrow + 16) && (jt + 63 >= wrow - 7);  // warp-uniform

        // ---- deferred PV half 1 of PREVIOUS tile (V buffer (it-1)&3 intact:
        //      prefetch writes (it+2)&3, which differs mod 4) ----
        if (it > 0) {
            const uint32_t vPrev = vBase + (uint32_t)(((it + 3) & 3) * 64 * AST) * 2;
            #pragma unroll
            for (int nt = 0; nt < 8; ++nt) {
                uint32_t vf[4];
                ldsm4(vf[0], vf[1], vf[2], vf[3],
                      vPrev + (uint32_t)((vbRow + nt * 8) * AST + vbColH + 32) * 2);
                mma_f16(of[nt], p1A, &vf[0]);
                mma_f16(of[nt], p1B, &vf[2]);
            }
        }

        // ---- QK half 0 (nt 0..3, keys jt+0..31) ----
        float sf[4][4];
        #pragma unroll
        for (int q = 0; q < 4; ++q) {
            sf[q][0] = sf[q][1] = sf[q][2] = sf[q][3] = 0.f;
            uint32_t kf[8];
            ldsm4(kf[0], kf[1], kf[2], kf[3],
                  kCur + (uint32_t)((kbRow + q * 8) * AST + kbColH) * 2);
            ldsm4(kf[4], kf[5], kf[6], kf[7],
                  kCur + (uint32_t)((kbRow + q * 8) * AST + kbColH + 32) * 2);
            #pragma unroll
            for (int ks = 0; ks < 4; ++ks)
                mma_f16(sf[q], qf[ks], &kf[ks * 2]);
        }
        if (band) {
            #pragma unroll
            for (int q = 0; q < 4; ++q) {
                const int c0 = jt + q * 8 + 2 * t, c1 = c0 + 1;
                if ((unsigned)(r0 - c0) < 8u) sf[q][0] = -1e30f;
                if ((unsigned)(r0 - c1) < 8u) sf[q][1] = -1e30f;
                if ((unsigned)(r1 - c0) < 8u) sf[q][2] = -1e30f;
                if ((unsigned)(r1 - c1) < 8u) sf[q][3] = -1e30f;
            }
        }

        // ---- pack0: P for keys 0..31 ----
        uint32_t p0A[4], p0B[4];
        p0A[0] = ex2h2(h2pack(sf[0][0], sf[0][1]));
        p0A[1] = ex2h2(h2pack(sf[0][2], sf[0][3]));
        p0A[2] = ex2h2(h2pack(sf[1][0], sf[1][1]));
        p0A[3] = ex2h2(h2pack(sf[1][2], sf[1][3]));
        p0B[0] = ex2h2(h2pack(sf[2][0], sf[2][1]));
        p0B[1] = ex2h2(h2pack(sf[2][2], sf[2][3]));
        p0B[2] = ex2h2(h2pack(sf[3][0], sf[3][1]));
        p0B[3] = ex2h2(h2pack(sf[3][2], sf[3][3]));

        // ---- QK half 1 (nt 4..7, keys jt+32..63) — hides pack0 latency ----
        #pragma unroll
        for (int q = 0; q < 4; ++q) {
            sf[q][0] = sf[q][1] = sf[q][2] = sf[q][3] = 0.f;
            uint32_t kf[8];
            ldsm4(kf[0], kf[1], kf[2], kf[3],
                  kCur + (uint32_t)((kbRow + (q + 4) * 8) * AST + kbColH) * 2);
            ldsm4(kf[4], kf[5], kf[6], kf[7],
                  kCur + (uint32_t)((kbRow + (q + 4) * 8) * AST + kbColH + 32) * 2);
            #pragma unroll
            for (int ks = 0; ks < 4; ++ks)
                mma_f16(sf[q], qf[ks], &kf[ks * 2]);
        }
        if (band) {
            #pragma unroll
            for (int q = 0; q < 4; ++q) {
                const int c0 = jt + (q + 4) * 8 + 2 * t, c1 = c0 + 1;
                if ((unsigned)(r0 - c0) < 8u) sf[q][0] = -1e30f;
                if ((unsigned)(r0 - c1) < 8u) sf[q][1] = -1e30f;
                if ((unsigned)(r1 - c0) < 8u) sf[q][2] = -1e30f;
                if ((unsigned)(r1 - c1) < 8u) sf[q][3] = -1e30f;
            }
        }

        // ---- l accumulation from p0 (FMA/ALU pipes) ----
        {
            __half2 h0 = __hadd2(__hadd2(u2h2(p0A[0]), u2h2(p0A[2])),
                                 __hadd2(u2h2(p0B[0]), u2h2(p0B[2])));
            __half2 h1 = __hadd2(__hadd2(u2h2(p0A[1]), u2h2(p0A[3])),
                                 __hadd2(u2h2(p0B[1]), u2h2(p0B[3])));
            float2 f0 = __half22float2(h0), f1 = __half22float2(h1);
            l0 += f0.x + f0.y;
            l1 += f1.x + f1.y;
        }

        // ---- PV half 0 (keys 0..31) ----
        #pragma unroll
        for (int nt = 0; nt < 8; ++nt) {
            uint32_t vf[4];
            ldsm4(vf[0], vf[1], vf[2], vf[3],
                  vCur + (uint32_t)((vbRow + nt * 8) * AST + vbColH) * 2);
            mma_f16(of[nt], p0A, &vf[0]);
            mma_f16(of[nt], p0B, &vf[2]);
        }

        // ---- pack1 (PV half1 deferred to next iteration) ----
        p1A[0] = ex2h2(h2pack(sf[0][0], sf[0][1]));
        p1A[1] = ex2h2(h2pack(sf[0][2], sf[0][3]));
        p1A[2] = ex2h2(h2pack(sf[1][0], sf[1][1]));
        p1A[3] = ex2h2(h2pack(sf[1][2], sf[1][3]));
        p1B[0] = ex2h2(h2pack(sf[2][0], sf[2][1]));
        p1B[1] = ex2h2(h2pack(sf[2][2], sf[2][3]));
        p1B[2] = ex2h2(h2pack(sf[3][0], sf[3][1]));
        p1B[3] = ex2h2(h2pack(sf[3][2], sf[3][3]));
        {
            __half2 h0 = __hadd2(__hadd2(u2h2(p1A[0]), u2h2(p1A[2])),
                                 __hadd2(u2h2(p1B[0]), u2h2(p1B[2])));
            __half2 h1 = __hadd2(__hadd2(u2h2(p1A[1]), u2h2(p1A[3])),
                                 __hadd2(u2h2(p1B[1]), u2h2(p1B[3])));
            float2 f0 = __half22float2(h0), f1 = __half22float2(h1);
            l0 += f0.x + f0.y;
            l1 += f1.x + f1.y;
        }
    }

    // ---- tail: PV half 1 of the last tile ----
    {
        const uint32_t vLast = vBase + (uint32_t)(((NTILES - 1) & 3) * 64 * AST) * 2;
        #pragma unroll
        for (int nt = 0; nt < 8; ++nt) {
            uint32_t vf[4];
            ldsm4(vf[0], vf[1], vf[2], vf[3],
                  vLast + (uint32_t)((vbRow + nt * 8) * AST + vbColH + 32) * 2);
            mma_f16(of[nt], p1A, &vf[0]);
            mma_f16(of[nt], p1B, &vf[2]);
        }
    }

    // ---- final l reduction over the quad ----
    l0 += __shfl_xor_sync(0xFFFFFFFF, l0, 1);
    l0 += __shfl_xor_sync(0xFFFFFFFF, l0, 2);
    l1 += __shfl_xor_sync(0xFFFFFFFF, l1, 1);
    l1 += __shfl_xor_sync(0xFFFFFFFF, l1, 2);

    // ---- normalize + write O (fp16) in [B,S,H*Dh] layout ----
    const float inv0 = 1.f / l0, inv1 = 1.f / l1;
    const int b = bh >> 3, hd = bh & 7;
    __half* O0 = g_O + ((size_t)(b * SS + wrow + g    ) * INNER + hd * DHH);
    __half* O1 = g_O + ((size_t)(b * SS + wrow + g + 8) * INNER + hd * DHH);
    #pragma unroll
    for (int nt = 0; nt < 8; ++nt) {
        const int d = nt * 8 + 2 * t;
        *(uint32_t*)(O0 + d) = h2pack(of[nt][0] * inv0, of[nt][1] * inv0);
        *(uint32_t*)(O1 + d) = h2pack(of[nt][2] * inv1, of[nt][3] * inv1);
    }
}

// ---------------------------------------------------------------------------
extern "C" void kernel_launch(void* const* d_in, const int* in_sizes, int n_in,
                              void* d_out, int out_size)
{
    const float* x      = (const float*)d_in[0];
    const float* W_qkv  = (const float*)d_in[1];
    const float* u_qkv  = (const float*)d_in[2];
    const float* sg_qkv = (const float*)d_in[3];
    const float* W_out  = (const float*)d_in[4];
    const float* b_out  = (const float*)d_in[5];
    const float* u_out  = (const float*)d_in[6];
    const float* sg_out = (const float*)d_in[7];
    const float* temp   = (const float*)d_in[8];
    float* out = (float*)d_out;

    __half* d_xT;  cudaGetSymbolAddress((void**)&d_xT,  g_xT);
    __half* d_WqT; cudaGetSymbolAddress((void**)&d_WqT, g_WqT);
    __half* d_WoT; cudaGetSymbolAddress((void**)&d_WoT, g_WoT);

    cudaFuncSetAttribute(gemm_mma_kernel<0, 4>,
                         cudaFuncAttributeMaxDynamicSharedMemorySize, GEMM_SMEM0);
    cudaFuncSetAttribute(gemm_mma_kernel<1, 2>,
                         cudaFuncAttributeMaxDynamicSharedMemorySize, GEMM_SMEM1);
    cudaFuncSetAttribute(attn_kernel,
                         cudaFuncAttributeMaxDynamicSharedMemorySize, ATTN_SMEM);

    cvtsn1_kernel<<<CVT_BLOCKS + 256, 256>>>((const float4*)x, (const float4*)W_qkv,
                                             (const float4*)W_out, W_qkv, W_out,
                                             u_qkv, u_out);
    sn2fin_kernel<<<16, 256>>>(W_qkv, W_out, sg_qkv, sg_out);

    gemm_mma_kernel<0, 4><<<dim3(NQKV / 128, MTOT / 128), 256, GEMM_SMEM0>>>(
        d_xT, d_WqT, nullptr, nullptr, NQKV, DD, 0, temp);
    attn_kernel<<<dim3(BB * HH, SS / 128), 256, ATTN_SMEM>>>();
    gemm_mma_kernel<1, 2><<<dim3(DD / 128, MTOT / 64), 256, GEMM_SMEM1>>>(
        (const __half*)nullptr, d_WoT, b_out, out, DD, INNER, 1, temp);
}

// round 17
// speedup vs baseline: 1.1311x; 1.1311x over previous
#include <cuda_runtime.h>
#include <cuda_fp16.h>
#include <math.h>
#include <stdint.h>

#define BB    2
#define SS    2048
#define DD    512
#define HH    8
#define DHH   64
#define INNER 512
#define MTOT  (BB*SS)      // 4096
#define NQKV  (3*INNER)    // 1536

// ---------------- scratch ----------------
__device__ float g_scale[2];
__device__ float g_t[2048];
__device__ float g_p2[16];
__device__ int   g_cnt;
__device__ __half g_Q[BB*HH*SS*DHH];        // [bh][row][dim] fp16, pre-scaled
__device__ __half g_K[BB*HH*SS*DHH];        // [bh][key][dim] fp16
__device__ __half g_V[BB*HH*SS*DHH];        // [bh][dim][key] fp16 (TRANSPOSED)
__device__ __half g_O[(size_t)MTOT*INNER];  // fp16
__device__ __half g_xT[(size_t)MTOT*DD];    // fp16 of x
__device__ __half g_WqT[(size_t)NQKV*DD];   // fp16 of W_qkv
__device__ __half g_WoT[(size_t)DD*INNER];  // fp16 of W_out

// ---------------- helpers ----------------
__device__ __forceinline__ uint32_t smem_u32(const void* p) {
    uint32_t a;
    asm("{ .reg .u64 t; cvta.to.shared.u64 t, %1; cvt.u32.u64 %0, t; }" : "=r"(a) : "l"(p));
    return a;
}
__device__ __forceinline__ uint32_t h2pack(float a, float b) {
    __half2 h = __floats2half2_rn(a, b);
    return *(uint32_t*)&h;
}
__device__ __forceinline__ uint32_t ex2h2(uint32_t x) {
    uint32_t y;
    asm("ex2.approx.f16x2 %0, %1;" : "=r"(y) : "r"(x));
    return y;
}
__device__ __forceinline__ void mma_f16(float* d, const uint32_t* a, const uint32_t* b) {
    asm volatile("mma.sync.aligned.m16n8k16.row.col.f32.f16.f16.f32 "
                 "{%0,%1,%2,%3}, {%4,%5,%6,%7}, {%8,%9}, {%0,%1,%2,%3};"
                 : "+f"(d[0]), "+f"(d[1]), "+f"(d[2]), "+f"(d[3])
                 : "r"(a[0]), "r"(a[1]), "r"(a[2]), "r"(a[3]), "r"(b[0]), "r"(b[1]));
}
__device__ __forceinline__ void ldsm4(uint32_t& r0, uint32_t& r1, uint32_t& r2, uint32_t& r3,
                                      uint32_t addr) {
    asm volatile("ldmatrix.sync.aligned.m8n8.x4.shared.b16 {%0,%1,%2,%3}, [%4];"
                 : "=r"(r0), "=r"(r1), "=r"(r2), "=r"(r3) : "r"(addr));
}
__device__ __forceinline__ void cp16(uint32_t dst, const void* src) {
    asm volatile("cp.async.cg.shared.global [%0], [%1], 16;" :: "r"(dst), "l"(src));
}
#define CP_COMMIT() asm volatile("cp.async.commit_group;" ::: "memory")
#define CP_WAIT(N)  asm volatile("cp.async.wait_group %0;" :: "n"(N) : "memory")

__device__ __forceinline__ __half2 u2h2(uint32_t u) { return *(__half2*)&u; }

// ---------------------------------------------------------------------------
// Fused kernel 1: fp32->fp16 conversion (blocks 0..1535) + sn1 (blocks 1536..1791)
// ---------------------------------------------------------------------------
#define M1 (MTOT*DD/8)
#define M2 (NQKV*DD/8)
#define M3 (DD*INNER/8)
#define CVT_BLOCKS ((M1 + M2 + M3) / 256)     // 1536

__global__ __launch_bounds__(256) void cvtsn1_kernel(const float4* __restrict__ x,
                                                     const float4* __restrict__ wq4,
                                                     const float4* __restrict__ wo4,
                                                     const float* __restrict__ Wq,
                                                     const float* __restrict__ Wo,
                                                     const float* __restrict__ uq,
                                                     const float* __restrict__ uo)
{
    if (blockIdx.x == 0 && threadIdx.x == 0) g_cnt = 0;

    if (blockIdx.x < CVT_BLOCKS) {
        const int i = blockIdx.x * 256 + threadIdx.x;
        const float4* src;
        uint4* dst;
        int j = i;
        if (j < M1)              { src = x;   dst = (uint4*)g_xT; }
        else if ((j -= M1) < M2) { src = wq4; dst = (uint4*)g_WqT; }
        else                     { j -= M2; src = wo4; dst = (uint4*)g_WoT; }
        float4 v0 = src[2 * j], v1 = src[2 * j + 1];
        uint4 o;
        o.x = h2pack(v0.x, v0.y);
        o.y = h2pack(v0.z, v0.w);
        o.z = h2pack(v1.x, v1.y);
        o.w = h2pack(v1.z, v1.w);
        dst[j] = o;
        return;
    }

    const int lb = blockIdx.x - CVT_BLOCKS;   // 0..255
    const int w = threadIdx.x >> 5, lane = threadIdx.x & 31;
    const bool isQ = lb < 192;
    const int rl = (isQ ? lb : lb - 192) * 8 + w;
    const float4* Wr = (const float4*)((isQ ? Wq : Wo) + (size_t)rl * DD);
    const float4* u4 = (const float4*)(isQ ? uq : uo);
    float acc = 0.f;
    for (int c = lane; c < DD / 4; c += 32) {
        float4 a = Wr[c], b = u4[c];
        acc += a.x * b.x + a.y * b.y + a.z * b.z + a.w * b.w;
    }
    #pragma unroll
    for (int s = 16; s > 0; s >>= 1) acc += __shfl_xor_sync(0xFFFFFFFF, acc, s);
    if (lane == 0) g_t[(isQ ? 0 : NQKV) + rl] = acc;
}

// ---------------------------------------------------------------------------
// Fused kernel 2: sn2 (16 blocks) + last-block finalize of both scales.
// ---------------------------------------------------------------------------
__global__ __launch_bounds__(256) void sn2fin_kernel(const float* __restrict__ Wq,
                                                     const float* __restrict__ Wo,
                                                     const float* __restrict__ s0,
                                                     const float* __restrict__ s1)
{
    __shared__ float red[256];
    __shared__ int isLast;
    const int t = threadIdx.x;
    const bool isQ = blockIdx.x < 8;
    const int cb = (isQ ? blockIdx.x : blockIdx.x - 8) * 64;
    const int R = isQ ? NQKV : INNER;
    const float* W = isQ ? Wq : Wo;
    const float* tv = g_t + (isQ ? 0 : NQKV);
    const int c = cb + (t & 63);
    const int seg = t >> 6;
    float acc = 0.f;
    for (int r = seg; r < R; r += 4) acc += W[(size_t)r * DD + c] * tv[r];
    red[t] = acc;
    __syncthreads();
    float s2 = 0.f;
    if (seg == 0) {
        float s = red[t] + red[t + 64] + red[t + 128] + red[t + 192];
        s2 = s * s;
    }
    red[t] = s2;
    __syncthreads();
    if (t < 32) red[t] += red[t + 32];
    __syncwarp();
    if (t < 32) {
        float v = red[t];
        #pragma unroll
        for (int s = 16; s > 0; s >>= 1) v += __shfl_xor_sync(0xFFFFFFFF, v, s);
        if (t == 0) g_p2[blockIdx.x] = v;
    }

    if (t == 0) {
        __threadfence();
        isLast = (atomicAdd(&g_cnt, 1) == 15);
    }
    __syncthreads();
    if (!isLast) return;

    float a0 = 0.f, a1 = 0.f;
    for (int r = t; r < NQKV; r += 256) { float v = g_t[r]; a0 += v * v; }
    for (int r = t; r < INNER; r += 256) { float v = g_t[NQKV + r]; a1 += v * v; }
    __syncthreads();
    red[t] = a0;
    __syncthreads();
    for (int s = 128; s > 0; s >>= 1) { if (t < s) red[t] += red[t + s]; __syncthreads(); }
    const float tt0 = red[0];
    __syncthreads();
    red[t] = a1;
    __syncthreads();
    for (int s = 128; s > 0; s >>= 1) { if (t < s) red[t] += red[t + s]; __syncthreads(); }
    const float tt1 = red[0];
    if (t == 0) {
        float ss0 = 0.f, ss1 = 0.f;
        #pragma unroll
        for (int i = 0; i < 8; ++i) { ss0 += g_p2[i]; ss1 += g_p2[8 + i]; }
        g_scale[0] = s0[0] * sqrtf(tt0 / ss0);
        g_scale[1] = s1[0] * sqrtf(tt1 / ss1);
    }
}

// ---------------------------------------------------------------------------
// fp16 mma GEMM (m16n8k16), 3-stage cp.async, K-chunk 32, ONE barrier/chunk.
// launch_bounds(256,2): cap regs at 128 so 2 CTAs/SM co-reside (smem 2x61.4KB
// fits 227KB). EPI=0: scatter Q/K/V(T). EPI=1: A=g_O, +bias fp32.
// ---------------------------------------------------------------------------
#define GST 40                                 // halves per row (80 B)
#define GEMM_SMEM (3 * 2 * 128 * GST * 2)      // 61440 B

template<int EPI>
__global__ __launch_bounds__(256, 2) void gemm_mma_kernel(const __half* __restrict__ Ain,
                                                          const __half* __restrict__ B,
                                                          const float* __restrict__ bias,
                                                          float* __restrict__ Cout,
                                                          int Ndim, int Kdim, int sidx,
                                                          const float* __restrict__ temp)
{
    extern __shared__ __half dsmh[];
    __half* sA = dsmh;                         // [3][128*GST]
    __half* sB = dsmh + 3 * 128 * GST;

    const __half* A = (EPI == 1) ? (const __half*)g_O : Ain;
    const int tid = threadIdx.x;
    const int wid = tid >> 5, lane = tid & 31;
    const int g = lane >> 2, t = lane & 3;
    const int wm = (wid >> 2) * 64;
    const int wn = (wid & 3) * 32;
    const int m0 = blockIdx.y * 128, n0 = blockIdx.x * 128;

    const uint32_t aBase = smem_u32(sA);
    const uint32_t bBase = smem_u32(sB);

    const int aRow = wm + (lane & 15);                 // + mt*16
    const int aColH = (lane >> 4) * 8;                 // + ks*16
    const int bRow = wn + (lane & 7);                  // + nt*8
    const int bColH = (lane >> 3) * 8;                 // covers k0..31

    auto prefetch = [&](int st, int k0) {
        #pragma unroll
        for (int p = 0; p < 2; ++p) {
            const int slot = tid + p * 256;
            const int row = slot >> 2, q = slot & 3;
            const uint32_t off = (uint32_t)(st * 128 * GST + row * GST + q * 8) * 2;
            cp16(aBase + off, A + (size_t)(m0 + row) * Kdim + k0 + q * 8);
            cp16(bBase + off, B + (size_t)(n0 + row) * Kdim + k0 + q * 8);
        }
        CP_COMMIT();
    };

    float acc[4][4][4];
    #pragma unroll
    for (int i = 0; i < 4; ++i)
        #pragma unroll
        for (int j = 0; j < 4; ++j)
            #pragma unroll
            for (int r = 0; r < 4; ++r) acc[i][j][r] = 0.f;

    const int nk = Kdim / 32;
    prefetch(0, 0);
    prefetch(1, 32);

    for (int kc = 0; kc < nk; ++kc) {
        if (kc + 1 < nk) { CP_WAIT(1); } else { CP_WAIT(0); }
        __syncthreads();
        if (kc + 2 < nk) prefetch((kc + 2) % 3, (kc + 2) * 32);

        const int cur = kc % 3;
        const uint32_t aCur = aBase + (uint32_t)(cur * 128 * GST) * 2;
        const uint32_t bCur = bBase + (uint32_t)(cur * 128 * GST) * 2;

        uint32_t bf[4][4];
        #pragma unroll
        for (int nt = 0; nt < 4; ++nt)
            ldsm4(bf[nt][0], bf[nt][1], bf[nt][2], bf[nt][3],
                  bCur + (uint32_t)((bRow + nt * 8) * GST + bColH) * 2);

        #pragma unroll
        for (int ks = 0; ks < 2; ++ks) {
            uint32_t af[4][4];
            #pragma unroll
            for (int mt = 0; mt < 4; ++mt)
                ldsm4(af[mt][0], af[mt][1], af[mt][2], af[mt][3],
                      aCur + (uint32_t)((aRow + mt * 16) * GST + aColH + ks * 16) * 2);
            #pragma unroll
            for (int mt = 0; mt < 4; ++mt)
                #pragma unroll
                for (int nt = 0; nt < 4; ++nt)
                    mma_f16(acc[mt][nt], af[mt], &bf[nt][ks * 2]);
        }
    }

    const float sc = g_scale[sidx];
    const float tsc = (EPI == 0) ? (expf(temp[0]) * 1.4426950408889634f) : 0.f;

    #pragma unroll
    for (int mt = 0; mt < 4; ++mt) {
        #pragma unroll
        for (int half = 0; half < 2; ++half) {
            const int m = m0 + wm + mt * 16 + g + half * 8;
            #pragma unroll
            for (int nt = 0; nt < 4; ++nt) {
                const int n = n0 + wn + nt * 8 + 2 * t;
                float v0 = acc[mt][nt][half * 2 + 0] * sc;
                float v1 = acc[mt][nt][half * 2 + 1] * sc;
                if (EPI == 0) {
                    const int seg = n >> 9, nn = n & 511;
                    const int head = nn >> 6, d = nn & 63;
                    const int b = m >> 11, s = m & 2047;
                    if (seg == 0) { v0 *= tsc; v1 *= tsc; }
                    if (seg == 2) {   // V transposed: [bh][dim][key]
                        __half* dst = g_V + (((size_t)(b * HH + head) * DHH + d) * SS + s);
                        dst[0]  = __float2half_rn(v0);
                        dst[SS] = __float2half_rn(v1);
                    } else {
                        __half* dst = (seg == 0) ? g_Q : g_K;
                        uint32_t pk = h2pack(v0, v1);
                        *(uint32_t*)(dst + (((size_t)(b * HH + head) * SS + s) * DHH + d)) = pk;
                    }
                } else {
                    float2 bb = *(const float2*)(bias + n);
                    float2 v = make_float2(v0 + bb.x, v1 + bb.y);
                    *(float2*)(Cout + (size_t)m * Ndim + n) = v;
                }
            }
        }
    }
}

// ---------------------------------------------------------------------------
// Flash attention (R15-proven schedule), fp16 m16n8k16, register-resident P:
//   QK(h0) -> pack0 -> QK(h1) -> laccum0 -> PV(h0) -> pack1 -> laccum1 -> PV(h1)
// l off the tensor pipe via __hadd2; band-skip masking; 3-stage cp.async.
// ---------------------------------------------------------------------------
#define AST 72                     // halves per row (144 B)
#define NSTG 3
#define ATTN_SMEM (NSTG * 2 * 64 * AST * 2)   // 55296 B
#define NTILES 32

__global__ __launch_bounds__(256, 2) void attn_kernel()
{
    extern __shared__ __half dsmh[];

    const int bh  = blockIdx.x;
    const int row0 = blockIdx.y * 128;
    const int tid = threadIdx.x;
    const int wid = tid >> 5, lane = tid & 31;
    const int g = lane >> 2, t = lane & 3;
    const int wrow = row0 + wid * 16;

    const uint32_t* Qu = (const uint32_t*)(g_Q + (size_t)bh * SS * DHH);  // 32 words/row
    const __half* Kg = g_K + (size_t)bh * SS * DHH;
    const __half* Vg = g_V + (size_t)bh * SS * DHH;   // [dim][key]

    const uint32_t kBase = smem_u32(dsmh);
    const uint32_t vBase = smem_u32(dsmh + NSTG * 64 * AST);

    const int kbRow = (lane & 7);             // + nt*8 (key row)
    const int kbColH = (lane >> 3) * 8;       // + c*32 (dim col)
    const int vbRow = (lane & 7);             // + nt*8 (dim row)
    const int vbColH = (lane >> 3) * 8;       // + ks2*32 (key col)

    auto prefetch = [&](int buf, int jt) {
        #pragma unroll
        for (int p = 0; p < 2; ++p) {          // K: 64 keys x 64 halves = 512 cp16
            const int s = tid + p * 256;
            const int row = s >> 3, q = s & 7;
            cp16(kBase + (uint32_t)(buf * 64 * AST + row * AST + q * 8) * 2,
                 Kg + (size_t)(jt + row) * DHH + q * 8);
        }
        #pragma unroll
        for (int p = 0; p < 2; ++p) {          // V: 64 dims x 64 keys
            const int s = tid + p * 256;
            const int row = s >> 3, q = s & 7;
            cp16(vBase + (uint32_t)(buf * 64 * AST + row * AST + q * 8) * 2,
                 Vg + (size_t)row * SS + jt + q * 8);
        }
        CP_COMMIT();
    };

    prefetch(0, 0);
    prefetch(1, 64);

    // Q a-frags (direct LDG; g_Q pre-scaled fp16): 4 ksteps of k16
    uint32_t qf[4][4];
    #pragma unroll
    for (int ks = 0; ks < 4; ++ks) {
        qf[ks][0] = Qu[(wrow + g    ) * 32 + ks * 8 + t    ];
        qf[ks][1] = Qu[(wrow + g + 8) * 32 + ks * 8 + t    ];
        qf[ks][2] = Qu[(wrow + g    ) * 32 + ks * 8 + t + 4];
        qf[ks][3] = Qu[(wrow + g + 8) * 32 + ks * 8 + t + 4];
    }

    float of[8][4];
    #pragma unroll
    for (int nt = 0; nt < 8; ++nt)
        #pragma unroll
        for (int r = 0; r < 4; ++r) of[nt][r] = 0.f;
    float l0 = 0.f, l1 = 0.f;

    const int r0 = wrow + g, r1 = wrow + g + 8;

    for (int it = 0; it < NTILES; ++it) {
        if (it + 1 < NTILES) { CP_WAIT(1); } else { CP_WAIT(0); }
        __syncthreads();
        if (it + 2 < NTILES) prefetch((it + 2) % 3, (it + 2) * 64);

        const int cur = it % 3;
        const uint32_t kCur = kBase + (uint32_t)(cur * 64 * AST) * 2;
        const uint32_t vCur = vBase + (uint32_t)(cur * 64 * AST) * 2;
        const int jt = it * 64;
        const bool band = (jt < wrow + 16) && (jt + 63 >= wrow - 7);  // warp-uniform

        // ---- QK half 0 (nt 0..3, keys jt+0..31) ----
        float sf[4][4];
        #pragma unroll
        for (int q = 0; q < 4; ++q) {
            sf[q][0] = sf[q][1] = sf[q][2] = sf[q][3] = 0.f;
            uint32_t kf[8];
            ldsm4(kf[0], kf[1], kf[2], kf[3],
                  kCur + (uint32_t)((kbRow + q * 8) * AST + kbColH) * 2);
            ldsm4(kf[4], kf[5], kf[6], kf[7],
                  kCur + (uint32_t)((kbRow + q * 8) * AST + kbColH + 32) * 2);
            #pragma unroll
            for (int ks = 0; ks < 4; ++ks)
                mma_f16(sf[q], qf[ks], &kf[ks * 2]);
        }
        if (band) {
            #pragma unroll
            for (int q = 0; q < 4; ++q) {
                const int c0 = jt + q * 8 + 2 * t, c1 = c0 + 1;
                if ((unsigned)(r0 - c0) < 8u) sf[q][0] = -1e30f;
                if ((unsigned)(r0 - c1) < 8u) sf[q][1] = -1e30f;
                if ((unsigned)(r1 - c0) < 8u) sf[q][2] = -1e30f;
                if ((unsigned)(r1 - c1) < 8u) sf[q][3] = -1e30f;
            }
        }

        // ---- pack0: P for keys 0..31 (a-frags) ----
        uint32_t p0A[4], p0B[4];
        p0A[0] = ex2h2(h2pack(sf[0][0], sf[0][1]));
        p0A[1] = ex2h2(h2pack(sf[0][2], sf[0][3]));
        p0A[2] = ex2h2(h2pack(sf[1][0], sf[1][1]));
        p0A[3] = ex2h2(h2pack(sf[1][2], sf[1][3]));
        p0B[0] = ex2h2(h2pack(sf[2][0], sf[2][1]));
        p0B[1] = ex2h2(h2pack(sf[2][2], sf[2][3]));
        p0B[2] = ex2h2(h2pack(sf[3][0], sf[3][1]));
        p0B[3] = ex2h2(h2pack(sf[3][2], sf[3][3]));

        // ---- QK half 1 (nt 4..7, keys jt+32..63) — hides pack0 latency ----
        #pragma unroll
        for (int q = 0; q < 4; ++q) {
            sf[q][0] = sf[q][1] = sf[q][2] = sf[q][3] = 0.f;
            uint32_t kf[8];
            ldsm4(kf[0], kf[1], kf[2], kf[3],
                  kCur + (uint32_t)((kbRow + (q + 4) * 8) * AST + kbColH) * 2);
            ldsm4(kf[4], kf[5], kf[6], kf[7],
                  kCur + (uint32_t)((kbRow + (q + 4) * 8) * AST + kbColH + 32) * 2);
            #pragma unroll
            for (int ks = 0; ks < 4; ++ks)
                mma_f16(sf[q], qf[ks], &kf[ks * 2]);
        }
        if (band) {
            #pragma unroll
            for (int q = 0; q < 4; ++q) {
                const int c0 = jt + (q + 4) * 8 + 2 * t, c1 = c0 + 1;
                if ((unsigned)(r0 - c0) < 8u) sf[q][0] = -1e30f;
                if ((unsigned)(r0 - c1) < 8u) sf[q][1] = -1e30f;
                if ((unsigned)(r1 - c0) < 8u) sf[q][2] = -1e30f;
                if ((unsigned)(r1 - c1) < 8u) sf[q][3] = -1e30f;
            }
        }

        // ---- l accumulation from p0 (FMA/ALU pipe, off tensor) ----
        {
            __half2 h0 = __hadd2(__hadd2(u2h2(p0A[0]), u2h2(p0A[2])),
                                 __hadd2(u2h2(p0B[0]), u2h2(p0B[2])));
            __half2 h1 = __hadd2(__hadd2(u2h2(p0A[1]), u2h2(p0A[3])),
                                 __hadd2(u2h2(p0B[1]), u2h2(p0B[3])));
            float2 f0 = __half22float2(h0), f1 = __half22float2(h1);
            l0 += f0.x + f0.y;
            l1 += f1.x + f1.y;
        }

        // ---- PV half 0 (keys 0..31) ----
        #pragma unroll
        for (int nt = 0; nt < 8; ++nt) {
            uint32_t vf[4];
            ldsm4(vf[0], vf[1], vf[2], vf[3],
                  vCur + (uint32_t)((vbRow + nt * 8) * AST + vbColH) * 2);
            mma_f16(of[nt], p0A, &vf[0]);
            mma_f16(of[nt], p0B, &vf[2]);
        }

        // ---- pack1 ----
        uint32_t p1A[4], p1B[4];
        p1A[0] = ex2h2(h2pack(sf[0][0], sf[0][1]));
        p1A[1] = ex2h2(h2pack(sf[0][2], sf[0][3]));
        p1A[2] = ex2h2(h2pack(sf[1][0], sf[1][1]));
        p1A[3] = ex2h2(h2pack(sf[1][2], sf[1][3]));
        p1B[0] = ex2h2(h2pack(sf[2][0], sf[2][1]));
        p1B[1] = ex2h2(h2pack(sf[2][2], sf[2][3]));
        p1B[2] = ex2h2(h2pack(sf[3][0], sf[3][1]));
        p1B[3] = ex2h2(h2pack(sf[3][2], sf[3][3]));

        // ---- l accumulation from p1 ----
        {
            __half2 h0 = __hadd2(__hadd2(u2h2(p1A[0]), u2h2(p1A[2])),
                                 __hadd2(u2h2(p1B[0]), u2h2(p1B[2])));
            __half2 h1 = __hadd2(__hadd2(u2h2(p1A[1]), u2h2(p1A[3])),
                                 __hadd2(u2h2(p1B[1]), u2h2(p1B[3])));
            float2 f0 = __half22float2(h0), f1 = __half22float2(h1);
            l0 += f0.x + f0.y;
            l1 += f1.x + f1.y;
        }

        // ---- PV half 1 (keys 32..63) ----
        #pragma unroll
        for (int nt = 0; nt < 8; ++nt) {
            uint32_t vf[4];
            ldsm4(vf[0], vf[1], vf[2], vf[3],
                  vCur + (uint32_t)((vbRow + nt * 8) * AST + vbColH + 32) * 2);
            mma_f16(of[nt], p1A, &vf[0]);
            mma_f16(of[nt], p1B, &vf[2]);
        }
    }

    // ---- final l reduction over the quad ----
    l0 += __shfl_xor_sync(0xFFFFFFFF, l0, 1);
    l0 += __shfl_xor_sync(0xFFFFFFFF, l0, 2);
    l1 += __shfl_xor_sync(0xFFFFFFFF, l1, 1);
    l1 += __shfl_xor_sync(0xFFFFFFFF, l1, 2);

    // ---- normalize + write O (fp16) in [B,S,H*Dh] layout ----
    const float inv0 = 1.f / l0, inv1 = 1.f / l1;
    const int b = bh >> 3, hd = bh & 7;
    __half* O0 = g_O + ((size_t)(b * SS + wrow + g    ) * INNER + hd * DHH);
    __half* O1 = g_O + ((size_t)(b * SS + wrow + g + 8) * INNER + hd * DHH);
    #pragma unroll
    for (int nt = 0; nt < 8; ++nt) {
        const int d = nt * 8 + 2 * t;
        *(uint32_t*)(O0 + d) = h2pack(of[nt][0] * inv0, of[nt][1] * inv0);
        *(uint32_t*)(O1 + d) = h2pack(of[nt][2] * inv1, of[nt][3] * inv1);
    }
}

// ---------------------------------------------------------------------------
extern "C" void kernel_launch(void* const* d_in, const int* in_sizes, int n_in,
                              void* d_out, int out_size)
{
    const float* x      = (const float*)d_in[0];
    const float* W_qkv  = (const float*)d_in[1];
    const float* u_qkv  = (const float*)d_in[2];
    const float* sg_qkv = (const float*)d_in[3];
    const float* W_out  = (const float*)d_in[4];
    const float* b_out  = (const float*)d_in[5];
    const float* u_out  = (const float*)d_in[6];
    const float* sg_out = (const float*)d_in[7];
    const float* temp   = (const float*)d_in[8];
    float* out = (float*)d_out;

    __half* d_xT;  cudaGetSymbolAddress((void**)&d_xT,  g_xT);
    __half* d_WqT; cudaGetSymbolAddress((void**)&d_WqT, g_WqT);
    __half* d_WoT; cudaGetSymbolAddress((void**)&d_WoT, g_WoT);

    cudaFuncSetAttribute(gemm_mma_kernel<0>,
                         cudaFuncAttributeMaxDynamicSharedMemorySize, GEMM_SMEM);
    cudaFuncSetAttribute(gemm_mma_kernel<1>,
                         cudaFuncAttributeMaxDynamicSharedMemorySize, GEMM_SMEM);
    cudaFuncSetAttribute(attn_kernel,
                         cudaFuncAttributeMaxDynamicSharedMemorySize, ATTN_SMEM);

    cvtsn1_kernel<<<CVT_BLOCKS + 256, 256>>>((const float4*)x, (const float4*)W_qkv,
                                             (const float4*)W_out, W_qkv, W_out,
                                             u_qkv, u_out);
    sn2fin_kernel<<<16, 256>>>(W_qkv, W_out, sg_qkv, sg_out);

    gemm_mma_kernel<0><<<dim3(NQKV / 128, MTOT / 128), 256, GEMM_SMEM>>>(
        d_xT, d_WqT, nullptr, nullptr, NQKV, DD, 0, temp);
    attn_kernel<<<dim3(BB * HH, SS / 128), 256, ATTN_SMEM>>>();
    gemm_mma_kernel<1><<<dim3(DD / 128, MTOT / 128), 256, GEMM_SMEM>>>(
        (const __half*)nullptr, d_WoT, b_out, out, DD, INNER, 1, temp);
}